// round 7
// baseline (speedup 1.0000x reference)
#include <cuda_runtime.h>
#include <cstdint>

#define W 131072
#define J 21
#define NB 20
#define BLOCK 256
#define GRID 1024
#define WPB (BLOCK / 32)
#define NWARP (GRID * WPB)                 // 8192 warps
#define CHUNK ((W + NWARP - 1) / NWARP)    // 16 frames per warp (exact)

// weights folded with denominators
#define C_PROJ   (1.0f / 42.0f)    // W_PROJ / (2*J)
#define C_BONE   (1.0f / 20.0f)    // W_BONE / (J-1)
#define C_SMOOTH (0.5f / 63.0f)    // W_SMOOTH / (3*J)
#define C_LIFT   (0.1f / 63.0f)    // W_LIFT / (3*J)

#define FULL 0xFFFFFFFFu

__device__ double g_acc;           // zero at load; last block resets each call
__device__ unsigned int g_count;   // wraps to 0 via atomicInc

__global__ __launch_bounds__(BLOCK)
void loss_kernel(const float* __restrict__ pose,   // [(W+1),3,J]
                 const float* __restrict__ cam,    // [W,2,3]
                 const float* __restrict__ p2d,    // [W,2,J]
                 const float* __restrict__ blen,   // [NB]
                 const float* __restrict__ lift,   // [W,3,NB]
                 const int*   __restrict__ bc,     // [NB,2]
                 const int*   __restrict__ lbc,    // [NB,2]
                 float* __restrict__ out)
{
    const int tid  = threadIdx.x;
    const int lane = tid & 31;
    const int wid  = tid >> 5;
    const int gw   = blockIdx.x * WPB + wid;
    const int f0   = gw * CHUNK;

    const bool jok = lane < J;     // joint-valid lanes
    const bool bok = lane < NB;    // bone-valid lanes

    // per-lane bone tables (read once, kept in registers)
    int ch = 0, pa = 0, lch = 0, lpa = 0;
    float bl = 0.0f;
    if (bok) {
        ch  = bc[2 * lane];
        pa  = bc[2 * lane + 1];
        lch = lbc[2 * lane];
        lpa = lbc[2 * lane + 1];
        bl  = blen[lane];
    }

    float acc = 0.0f;

    if (f0 < W) {
        const int fend = min(W, f0 + CHUNK);

        // ---- lead-in: p0 = pose frame f0, pm = pose frame max(f0-1,0) ----
        const float* pA = pose + (size_t)f0 * 63;
        float x0 = jok ? pA[lane]          : 0.0f;
        float y0 = jok ? pA[J + lane]      : 0.0f;
        float z0 = jok ? pA[2 * J + lane]  : 0.0f;
        const float* pB = pose + (size_t)(f0 > 0 ? f0 - 1 : 0) * 63;
        float xm = jok ? pB[lane]          : 0.0f;
        float ym = jok ? pB[J + lane]      : 0.0f;
        float zm = jok ? pB[2 * J + lane]  : 0.0f;

        // ---- frame-0 bone term (owned by the warp whose chunk starts at 0) ----
        if (f0 == 0) {
            float dx = __shfl_sync(FULL, x0, ch) - __shfl_sync(FULL, x0, pa);
            float dy = __shfl_sync(FULL, y0, ch) - __shfl_sync(FULL, y0, pa);
            float dz = __shfl_sync(FULL, z0, ch) - __shfl_sync(FULL, z0, pa);
            float len = dx * dx + dy * dy + dz * dz;
            float e = len - bl;
            if (bok) acc += C_BONE * e * e;
        }

        for (int w = f0; w < fend; w++) {
            // ---- load frame w+1 (the only pose DRAM read per iteration) ----
            const float* pf = pose + (size_t)(w + 1) * 63;
            float x1 = jok ? pf[lane]         : 0.0f;
            float y1 = jok ? pf[J + lane]     : 0.0f;
            float z1 = jok ? pf[2 * J + lane] : 0.0f;

            const float* c = cam + (size_t)w * 6;       // uniform broadcasts
            float c0 = c[0], c1 = c[1], c2 = c[2];
            float c3 = c[3], c4 = c[4], c5 = c[5];

            const float* q = p2d + (size_t)w * 42;
            float qx = jok ? q[lane]     : 0.0f;
            float qy = jok ? q[J + lane] : 0.0f;

            const float* ld = lift + (size_t)w * 60;
            float ldx = bok ? ld[lane]          : 0.0f;
            float ldy = bok ? ld[NB + lane]     : 0.0f;
            float ldz = bok ? ld[2 * NB + lane] : 0.0f;

            // ---- projection ----
            float px = c0 * x1 + c1 * y1 + c2 * z1 - qx;
            float py = c3 * x1 + c4 * y1 + c5 * z1 - qy;
            if (jok) acc += C_PROJ * (px * px + py * py);

            // ---- smoothness (second difference), valid for w >= 1 ----
            if (w >= 1) {
                float a0 = x1 - 2.0f * x0 + xm;
                float a1 = y1 - 2.0f * y0 + ym;
                float a2 = z1 - 2.0f * z0 + zm;
                if (jok) acc += C_SMOOTH * (a0 * a0 + a1 * a1 + a2 * a2);
            }

            // ---- bone length (frame w+1), via warp shuffles ----
            float bx = __shfl_sync(FULL, x1, ch) - __shfl_sync(FULL, x1, pa);
            float by = __shfl_sync(FULL, y1, ch) - __shfl_sync(FULL, y1, pa);
            float bz = __shfl_sync(FULL, z1, ch) - __shfl_sync(FULL, z1, pa);
            {
                float len = bx * bx + by * by + bz * bz;
                float e = len - bl;
                if (bok) acc += C_BONE * e * e;
            }

            // ---- lift direction ----
            float ux = __shfl_sync(FULL, x1, lch) - __shfl_sync(FULL, x1, lpa);
            float uy = __shfl_sync(FULL, y1, lch) - __shfl_sync(FULL, y1, lpa);
            float uz = __shfl_sync(FULL, z1, lch) - __shfl_sync(FULL, z1, lpa);
            {
                float n2 = ux * ux + uy * uy + uz * uz;
                float inv = bok ? (1.0f / sqrtf(n2)) : 0.0f;
                float ex = ldx - ux * inv;
                float ey = ldy - uy * inv;
                float ez = ldz - uz * inv;
                if (bok) acc += C_LIFT * (ex * ex + ey * ey + ez * ez);
            }

            // rotate frame registers
            xm = x0; ym = y0; zm = z0;
            x0 = x1; y0 = y1; z0 = z1;
        }
    }

    // ---- warp reduction ----
    #pragma unroll
    for (int off = 16; off > 0; off >>= 1)
        acc += __shfl_down_sync(FULL, acc, off);

    __shared__ float warp_sums[WPB];
    __shared__ bool  is_last;
    if (lane == 0) warp_sums[wid] = acc;
    __syncthreads();

    if (wid == 0) {
        float v = (lane < WPB) ? warp_sums[lane] : 0.0f;
        #pragma unroll
        for (int off = 4; off > 0; off >>= 1)
            v += __shfl_down_sync(FULL, v, off);
        if (lane == 0) {
            atomicAdd(&g_acc, (double)v);
            __threadfence();
            unsigned int ticket = atomicInc(&g_count, GRID - 1);
            is_last = (ticket == GRID - 1);
        }
    }
    __syncthreads();

    if (is_last && tid == 0) {
        __threadfence();
        out[0] = (float)g_acc;
        g_acc = 0.0;   // reset for next graph replay (g_count already wrapped)
        __threadfence();
    }
}

extern "C" void kernel_launch(void* const* d_in, const int* in_sizes, int n_in,
                              void* d_out, int out_size)
{
    const float* pose = (const float*)d_in[0];
    const float* cam  = (const float*)d_in[1];
    const float* p2d  = (const float*)d_in[2];
    const float* blen = (const float*)d_in[3];
    const float* lift = (const float*)d_in[4];
    const int*   bc   = (const int*)d_in[5];
    const int*   lbc  = (const int*)d_in[6];
    float* out = (float*)d_out;

    loss_kernel<<<GRID, BLOCK>>>(pose, cam, p2d, blen, lift, bc, lbc, out);
}

// round 8
// speedup vs baseline: 1.0559x; 1.0559x over previous
#include <cuda_runtime.h>
#include <cstdint>

#define W 131072
#define J 21
#define NB 20
#define BLOCK 256
#define GRID 1024
#define WPB (BLOCK / 32)
#define NWARP (GRID * WPB)                 // 8192 warps
#define CHUNK ((W + NWARP - 1) / NWARP)    // 16 frames per warp (exact)

// weights folded with denominators
#define C_PROJ   (1.0f / 42.0f)    // W_PROJ / (2*J)
#define C_BONE   (1.0f / 20.0f)    // W_BONE / (J-1)
#define C_SMOOTH (0.5f / 63.0f)    // W_SMOOTH / (3*J)
#define C_LIFT   (0.1f / 63.0f)    // W_LIFT / (3*J)

#define FULL 0xFFFFFFFFu

__device__ double g_acc;           // zero at load; last block resets each call
__device__ unsigned int g_count;   // wraps to 0 via atomicInc

__global__ __launch_bounds__(BLOCK)
void loss_kernel(const float* __restrict__ pose,   // [(W+1),3,J]
                 const float* __restrict__ cam,    // [W,2,3]
                 const float* __restrict__ p2d,    // [W,2,J]
                 const float* __restrict__ blen,   // [NB]
                 const float* __restrict__ lift,   // [W,3,NB]
                 const int*   __restrict__ bc,     // [NB,2]
                 const int*   __restrict__ lbc,    // [NB,2]
                 float* __restrict__ out)
{
    const int tid  = threadIdx.x;
    const int lane = tid & 31;
    const int wid  = tid >> 5;
    const int gw   = blockIdx.x * WPB + wid;
    const int f0   = gw * CHUNK;

    const bool jok = lane < J;     // joint-valid lanes
    const bool bok = lane < NB;    // bone-valid lanes

    // per-lane bone tables (read once, kept in registers)
    int ch = 0, pa = 0, lch = 0, lpa = 0;
    float bl = 0.0f;
    if (bok) {
        ch  = bc[2 * lane];
        pa  = bc[2 * lane + 1];
        lch = lbc[2 * lane];
        lpa = lbc[2 * lane + 1];
        bl  = blen[lane];
    }

    float acc = 0.0f;

    if (f0 < W) {
        const int fend = min(W, f0 + CHUNK);

        // ---- lead-in: p0 = pose frame f0, pm = pose frame max(f0-1,0) ----
        const float* pA = pose + (size_t)f0 * 63;
        float x0 = jok ? pA[lane]          : 0.0f;
        float y0 = jok ? pA[J + lane]      : 0.0f;
        float z0 = jok ? pA[2 * J + lane]  : 0.0f;
        const float* pB = pose + (size_t)(f0 > 0 ? f0 - 1 : 0) * 63;
        float xm = jok ? pB[lane]          : 0.0f;
        float ym = jok ? pB[J + lane]      : 0.0f;
        float zm = jok ? pB[2 * J + lane]  : 0.0f;

        // ---- frame-0 bone term (owned by the warp whose chunk starts at 0) ----
        if (f0 == 0) {
            float dx = __shfl_sync(FULL, x0, ch) - __shfl_sync(FULL, x0, pa);
            float dy = __shfl_sync(FULL, y0, ch) - __shfl_sync(FULL, y0, pa);
            float dz = __shfl_sync(FULL, z0, ch) - __shfl_sync(FULL, z0, pa);
            float len = dx * dx + dy * dy + dz * dz;
            float e = len - bl;
            if (bok) acc += C_BONE * e * e;
        }

        for (int w = f0; w < fend; w++) {
            // ---- load frame w+1 (the only pose DRAM read per iteration) ----
            const float* pf = pose + (size_t)(w + 1) * 63;
            float x1 = jok ? pf[lane]         : 0.0f;
            float y1 = jok ? pf[J + lane]     : 0.0f;
            float z1 = jok ? pf[2 * J + lane] : 0.0f;

            const float* c = cam + (size_t)w * 6;       // uniform broadcasts
            float c0 = c[0], c1 = c[1], c2 = c[2];
            float c3 = c[3], c4 = c[4], c5 = c[5];

            const float* q = p2d + (size_t)w * 42;
            float qx = jok ? q[lane]     : 0.0f;
            float qy = jok ? q[J + lane] : 0.0f;

            const float* ld = lift + (size_t)w * 60;
            float ldx = bok ? ld[lane]          : 0.0f;
            float ldy = bok ? ld[NB + lane]     : 0.0f;
            float ldz = bok ? ld[2 * NB + lane] : 0.0f;

            // ---- projection ----
            float px = c0 * x1 + c1 * y1 + c2 * z1 - qx;
            float py = c3 * x1 + c4 * y1 + c5 * z1 - qy;
            if (jok) acc += C_PROJ * (px * px + py * py);

            // ---- smoothness (second difference), valid for w >= 1 ----
            if (w >= 1) {
                float a0 = x1 - 2.0f * x0 + xm;
                float a1 = y1 - 2.0f * y0 + ym;
                float a2 = z1 - 2.0f * z0 + zm;
                if (jok) acc += C_SMOOTH * (a0 * a0 + a1 * a1 + a2 * a2);
            }

            // ---- bone length (frame w+1), via warp shuffles ----
            float bx = __shfl_sync(FULL, x1, ch) - __shfl_sync(FULL, x1, pa);
            float by = __shfl_sync(FULL, y1, ch) - __shfl_sync(FULL, y1, pa);
            float bz = __shfl_sync(FULL, z1, ch) - __shfl_sync(FULL, z1, pa);
            {
                float len = bx * bx + by * by + bz * bz;
                float e = len - bl;
                if (bok) acc += C_BONE * e * e;
            }

            // ---- lift direction ----
            float ux = __shfl_sync(FULL, x1, lch) - __shfl_sync(FULL, x1, lpa);
            float uy = __shfl_sync(FULL, y1, lch) - __shfl_sync(FULL, y1, lpa);
            float uz = __shfl_sync(FULL, z1, lch) - __shfl_sync(FULL, z1, lpa);
            {
                float n2 = ux * ux + uy * uy + uz * uz;
                float inv = bok ? (1.0f / sqrtf(n2)) : 0.0f;
                float ex = ldx - ux * inv;
                float ey = ldy - uy * inv;
                float ez = ldz - uz * inv;
                if (bok) acc += C_LIFT * (ex * ex + ey * ey + ez * ez);
            }

            // rotate frame registers
            xm = x0; ym = y0; zm = z0;
            x0 = x1; y0 = y1; z0 = z1;
        }
    }

    // ---- warp reduction ----
    #pragma unroll
    for (int off = 16; off > 0; off >>= 1)
        acc += __shfl_down_sync(FULL, acc, off);

    __shared__ float warp_sums[WPB];
    __shared__ bool  is_last;
    if (lane == 0) warp_sums[wid] = acc;
    __syncthreads();

    if (wid == 0) {
        float v = (lane < WPB) ? warp_sums[lane] : 0.0f;
        #pragma unroll
        for (int off = 4; off > 0; off >>= 1)
            v += __shfl_down_sync(FULL, v, off);
        if (lane == 0) {
            atomicAdd(&g_acc, (double)v);
            __threadfence();
            unsigned int ticket = atomicInc(&g_count, GRID - 1);
            is_last = (ticket == GRID - 1);
        }
    }
    __syncthreads();

    if (is_last && tid == 0) {
        __threadfence();
        out[0] = (float)g_acc;
        g_acc = 0.0;   // reset for next graph replay (g_count already wrapped)
        __threadfence();
    }
}

extern "C" void kernel_launch(void* const* d_in, const int* in_sizes, int n_in,
                              void* d_out, int out_size)
{
    const float* pose = (const float*)d_in[0];
    const float* cam  = (const float*)d_in[1];
    const float* p2d  = (const float*)d_in[2];
    const float* blen = (const float*)d_in[3];
    const float* lift = (const float*)d_in[4];
    const int*   bc   = (const int*)d_in[5];
    const int*   lbc  = (const int*)d_in[6];
    float* out = (float*)d_out;

    loss_kernel<<<GRID, BLOCK>>>(pose, cam, p2d, blen, lift, bc, lbc, out);
}